// round 10
// baseline (speedup 1.0000x reference)
#include <cuda_runtime.h>
#include <math.h>

#define BB 2
#define MM 4096
#define CC 256
#define HW 64
#define NBINS 512
#define QCAP 96
#define NITEMS 2048
#define NPOS_MAX 169
#define PSTRH 132                 // position stride in floats (gmem AND smem)
#define DSTR 172
#define PW0 73
#define TOTPOS 7924               // 73^2 + 41^2 + 25^2 + 17^2

// padded pyramid: [b][half][pos][132]
__device__ __align__(1024) float g_pyr2[BB * 2 * TOTPOS * PSTRH];
__device__ int g_cnt[NBINS];
__device__ int g_qlist[NBINS * QCAP];
__device__ int g_work;

__constant__ int c_lvl_base[4] = {0, 5329, 7010, 7635};
__constant__ int c_lvl_pw[4]   = {73, 41, 25, 17};

// ---------------- helpers ---------------------------------------------------
__device__ __forceinline__ void fma2(unsigned long long& d, unsigned long long a,
                                     unsigned long long b) {
    asm("fma.rn.f32x2 %0, %1, %2, %0;" : "+l"(d) : "l"(a), "l"(b));
}
__device__ __forceinline__ float unpack_sum(unsigned long long v) {
    return __uint_as_float((unsigned)v) + __uint_as_float((unsigned)(v >> 32));
}
__device__ __forceinline__ void bulkcp(unsigned dst, const void* src,
                                       unsigned bytes, unsigned mbar) {
    asm volatile("cp.async.bulk.shared::cluster.global.mbarrier::complete_tx::bytes "
                 "[%0], [%1], %2, [%3];" :: "r"(dst), "l"(src), "r"(bytes), "r"(mbar)
                 : "memory");
}
__device__ __forceinline__ void mbar_init(unsigned mbar, unsigned cnt) {
    asm volatile("mbarrier.init.shared.b64 [%0], %1;" :: "r"(mbar), "r"(cnt) : "memory");
}
__device__ __forceinline__ void mbar_expect(unsigned mbar, unsigned bytes) {
    asm volatile("mbarrier.arrive.expect_tx.shared.b64 _, [%0], %1;"
                 :: "r"(mbar), "r"(bytes) : "memory");
}
__device__ __forceinline__ void mbar_wait(unsigned mbar, unsigned parity) {
    unsigned done;
    asm volatile("{\n\t.reg .pred p;\n\t"
                 "mbarrier.try_wait.parity.shared.b64 p, [%1], %2;\n\t"
                 "selp.b32 %0, 1, 0, p;\n\t}" : "=r"(done) : "r"(mbar), "r"(parity)
                 : "memory");
    while (!done)
        asm volatile("{\n\t.reg .pred p;\n\t"
                     "mbarrier.try_wait.parity.shared.b64 p, [%1], %2, 0x989680;\n\t"
                     "selp.b32 %0, 1, 0, p;\n\t}" : "=r"(done)
                     : "r"(mbar), "r"(parity) : "memory");
}

// ---------------- kernel 1: transpose + zero counters -----------------------
__global__ void transpose_kernel(const float* __restrict__ f2) {
    __shared__ float tile[32][33];
    int b = blockIdx.z, p0 = blockIdx.x * 32, c0 = blockIdx.y * 32;
    int tx = threadIdx.x, ty = threadIdx.y;
    if (blockIdx.x == 0 && blockIdx.y == 0 && blockIdx.z == 0) {
        int t = ty * 32 + tx;
        if (t < NBINS) g_cnt[t] = 0;
        if (t == 0) g_work = 0;
    }
    tile[ty][tx] = f2[((size_t)b * CC + (c0 + ty)) * (HW * HW) + p0 + tx];
    __syncthreads();
    int p = p0 + ty, y = p >> 6, x = p & 63;
    int c = c0 + tx, h = c >> 7, cc = c & 127;
    int pos = (y + 4) * PW0 + (x + 4);
    g_pyr2[((size_t)(b * 2 + h) * TOTPOS + pos) * PSTRH + cc] = tile[tx][ty];
}

// ---------------- kernel 2: all pooled levels from L0 ------------------------
__global__ void pool_all_kernel() {
    int r = blockIdx.x;
    int b = r / 1344, t = r - b * 1344;
    int l, W, i;
    if (t < 1024)      { l = 1; W = 32; i = t; }
    else if (t < 1280) { l = 2; W = 16; i = t - 1024; }
    else               { l = 3; W = 8;  i = t - 1280; }
    int y = i / W, x = i - (i / W) * W;
    int S = 1 << l;
    int c = threadIdx.x;
    int h = c >> 7, cc = c & 127;
    const float* in = g_pyr2 + (size_t)(b * 2 + h) * TOTPOS * PSTRH + cc;
    float s = 0.f;
    for (int dy = 0; dy < S; dy++)
        for (int dx = 0; dx < S; dx++)
            s += in[(size_t)((y * S + dy + 4) * PW0 + (x * S + dx + 4)) * PSTRH];
    g_pyr2[((size_t)(b * 2 + h) * TOTPOS + c_lvl_base[l]
            + (y + 4) * c_lvl_pw[l] + (x + 4)) * PSTRH + cc] = s / (float)(S * S);
}

// ---------------- kernel 3: histogram + halo zeroing ------------------------
__global__ void hist_kernel(const float* __restrict__ cen) {
    int t = blockIdx.x * blockDim.x + threadIdx.x;

    for (int p = t; p < BB * 2 * TOTPOS; p += 32 * 256) {
        int pp = p % TOTPOS;
        int l = pp < 5329 ? 0 : (pp < 7010 ? 1 : (pp < 7635 ? 2 : 3));
        int pwl = c_lvl_pw[l];
        int r = pp - c_lvl_base[l];
        int y = r / pwl, x = r - (r / pwl) * pwl;
        int W = pwl - 9;
        if (x < 4 || x >= W + 4 || y < 4 || y >= W + 4) {
            float4* dst = (float4*)(g_pyr2 + (size_t)p * PSTRH);
            #pragma unroll 4
            for (int i = 0; i < PSTRH / 4; i++) dst[i] = make_float4(0.f, 0.f, 0.f, 0.f);
        }
    }

    if (t < BB * MM) {
        float cx = cen[2 * t], cy = cen[2 * t + 1];
        int bx = ((int)cx) >> 2;  bx = bx < 0 ? 0 : (bx > 15 ? 15 : bx);
        int by = ((int)cy) >> 2;  by = by < 0 ? 0 : (by > 15 ? 15 : by);
        int b = t / MM, m = t - b * MM;
        int bin = (b << 8) | (by << 4) | bx;
        int pos = atomicAdd(&g_cnt[bin], 1);
        if (pos < QCAP) g_qlist[bin * QCAP + pos] = m;
    }
}

// ---------------- geometry & staging ----------------------------------------
struct Geo { int lvl, bin, b, px0, py0, pw, ph, Npos, pwp, lbase, nq, nch; };

__device__ __forceinline__ Geo get_geo(int item) {
    Geo g;
    g.lvl = item & 3; g.bin = item >> 2; g.b = g.bin >> 8;
    int by = (g.bin >> 4) & 15, bx = g.bin & 15;
    int ixmin = (4 * bx) >> g.lvl, ixmax = (4 * bx + 3) >> g.lvl;
    int iymin = (4 * by) >> g.lvl, iymax = (4 * by + 3) >> g.lvl;
    g.px0 = ixmin - 4; g.py0 = iymin - 4;
    g.pw = ixmax - ixmin + 10; g.ph = iymax - iymin + 10;
    g.Npos = g.pw * g.ph;
    g.pwp = c_lvl_pw[g.lvl]; g.lbase = c_lvl_base[g.lvl];
    int n = g_cnt[g.bin]; if (n > QCAP) n = QCAP;
    g.nq = n; g.nch = (n + 15) >> 4;
    return g;
}

__device__ __forceinline__ int next_item() {
    while (true) {
        int it = atomicAdd(&g_work, 1);
        if (it >= NITEMS) return NITEMS;
        if (g_cnt[it >> 2] > 0) return it;
    }
}

// stage one (chunk, half) step: patch rows + 16 A rows. Warp 0 only.
__device__ __forceinline__ void issue_step(const Geo& g, int ch, int h,
                                           unsigned Pb, unsigned Ab, unsigned mbar,
                                           const float* __restrict__ f1, int lane) {
    unsigned rowB = (unsigned)(g.pw * PSTRH * 4);
    if (lane == 0) mbar_expect(mbar, (unsigned)g.ph * rowB + 16u * 512u);
    const float* pbase = g_pyr2
        + ((size_t)(g.b * 2 + h) * TOTPOS + g.lbase
           + (size_t)(g.py0 + 4) * g.pwp + (g.px0 + 4)) * PSTRH;
    for (int ly = lane; ly < g.ph; ly += 32)
        bulkcp(Pb + (unsigned)(ly * g.pw * PSTRH) * 4u,
               pbase + (size_t)ly * g.pwp * PSTRH, rowB, mbar);
    if (lane < 16) {
        int qcnt = g.nq - 16 * ch; if (qcnt > 16) qcnt = 16;
        int qv = lane < qcnt ? lane : 0;
        int m = g_qlist[g.bin * QCAP + 16 * ch + qv];
        bulkcp(Ab + (unsigned)(lane * PSTRH) * 4u,
               f1 + ((size_t)g.b * MM + m) * CC + h * 128, 512u, mbar);
    }
}

// ---------------- GEMM inner loop (templated) --------------------------------
template <int NQI, int NSW>
__device__ __forceinline__ void gemm_half(const float* __restrict__ As,
                                          const float* __restrict__ Ps,
                                          int qsel, const int* poff,
                                          unsigned long long acc[4][3]) {
    #pragma unroll 2
    for (int c = 0; c < 128; c += 4) {
        ulonglong2 a[NQI], p[NSW];
        #pragma unroll
        for (int qi = 0; qi < NQI; qi++)
            a[qi] = *(const ulonglong2*)&As[(qsel + 4 * qi) * PSTRH + c];
        #pragma unroll
        for (int pi = 0; pi < NSW; pi++)
            p[pi] = *(const ulonglong2*)&Ps[poff[pi] + c];
        #pragma unroll
        for (int qi = 0; qi < NQI; qi++)
            #pragma unroll
            for (int pi = 0; pi < NSW; pi++) {
                fma2(acc[qi][pi], a[qi].x, p[pi].x);
                fma2(acc[qi][pi], a[qi].y, p[pi].y);
            }
    }
}

#define DISPATCH_NQI(NSW_)                                                     \
    switch (nqi) {                                                             \
        case 4: gemm_half<4, NSW_>(Asb, Psb, qsel, poff, acc); break;          \
        case 3: gemm_half<3, NSW_>(Asb, Psb, qsel, poff, acc); break;          \
        case 2: gemm_half<2, NSW_>(Asb, Psb, qsel, poff, acc); break;          \
        default: gemm_half<1, NSW_>(Asb, Psb, qsel, poff, acc); break;         \
    }

// ---------------- main persistent kernel -------------------------------------
__global__ __launch_bounds__(256, 1) void corr_kernel(const float* __restrict__ f1,
                                                      const float* __restrict__ cen,
                                                      float* __restrict__ out) {
    extern __shared__ float sm[];
    float* PsP[2] = { sm, sm + NPOS_MAX * PSTRH };
    float* AsP[2] = { sm + 2 * NPOS_MAX * PSTRH,
                      sm + 2 * NPOS_MAX * PSTRH + 16 * PSTRH };
    float* Ds = sm + 2 * NPOS_MAX * PSTRH + 32 * PSTRH;
    __shared__ __align__(8) unsigned long long mb[2];
    __shared__ int s_next;

    int tid = threadIdx.x, lane = tid & 31, w = tid >> 5;
    int qsel = lane >> 3, psel = lane & 7;

    unsigned Pb[2] = { (unsigned)__cvta_generic_to_shared(PsP[0]),
                       (unsigned)__cvta_generic_to_shared(PsP[1]) };
    unsigned Ab[2] = { (unsigned)__cvta_generic_to_shared(AsP[0]),
                       (unsigned)__cvta_generic_to_shared(AsP[1]) };
    unsigned mbB[2] = { (unsigned)__cvta_generic_to_shared(&mb[0]),
                        (unsigned)__cvta_generic_to_shared(&mb[1]) };

    if (tid == 0) {
        mbar_init(mbB[0], 1); mbar_init(mbB[1], 1);
        s_next = next_item();
    }
    __syncthreads();
    int item = s_next;
    __syncthreads();                       // all read before tid0 overwrites
    if (item >= NITEMS) return;
    Geo g = get_geo(item);
    if (tid == 0) s_next = next_item();    // published by first loop-top sync
    int cur = 0;
    int par[2] = {0, 0};
    if (w == 0) issue_step(g, 0, 0, Pb[0], Ab[0], mbB[0], f1, lane);

    while (true) {
        float scale = 1.0f / (float)(1 << g.lvl);
        int nstrips = (g.Npos + 7) >> 3;
        int nsw = (nstrips > w) ? ((nstrips - w + 7) >> 3) : 0;
        int poff[3];
        #pragma unroll
        for (int pi = 0; pi < 3; pi++) {
            int p = (w + 8 * pi) * 8 + psel;
            poff[pi] = ((p < g.Npos) ? p : (g.Npos - 1)) * PSTRH;
        }

        for (int ch = 0; ch < g.nch; ch++) {
            int qcnt = g.nq - 16 * ch; if (qcnt > 16) qcnt = 16;
            int nqi = (qcnt + 3) >> 2;

            unsigned long long acc[4][3];
            #pragma unroll
            for (int qi = 0; qi < 4; qi++)
                #pragma unroll
                for (int pi = 0; pi < 3; pi++) acc[qi][pi] = 0ull;

            for (int h = 0; h < 2; h++) {
                __syncthreads();           // buf[cur^1] free; s_next visible
                if (w == 0) {              // stage the NEXT step into cur^1
                    if (h == 0) {
                        issue_step(g, ch, 1, Pb[cur ^ 1], Ab[cur ^ 1], mbB[cur ^ 1], f1, lane);
                    } else if (ch + 1 < g.nch) {
                        issue_step(g, ch + 1, 0, Pb[cur ^ 1], Ab[cur ^ 1], mbB[cur ^ 1], f1, lane);
                    } else {
                        int it2 = s_next;
                        if (it2 < NITEMS) {
                            Geo gn = get_geo(it2);
                            issue_step(gn, 0, 0, Pb[cur ^ 1], Ab[cur ^ 1], mbB[cur ^ 1], f1, lane);
                        }
                    }
                }
                mbar_wait(mbB[cur], par[cur] & 1); par[cur]++;

                const float* Psb = PsP[cur];
                const float* Asb = AsP[cur];
                switch (nsw) {
                    case 3: DISPATCH_NQI(3); break;
                    case 2: DISPATCH_NQI(2); break;
                    case 1: DISPATCH_NQI(1); break;
                    default: break;
                }
                cur ^= 1;
            }

            // ---- dump D ----
            #pragma unroll
            for (int pi = 0; pi < 3; pi++) {
                if (pi < nsw) {
                    int p = (w + 8 * pi) * 8 + psel;
                    if (p < g.Npos) {
                        #pragma unroll
                        for (int qi = 0; qi < 4; qi++)
                            Ds[(qsel + 4 * qi) * DSTR + p] = unpack_sum(acc[qi][pi]);
                    }
                }
            }
            __syncthreads();

            // ---- bilinear epilogue ----
            for (int qq = w; qq < qcnt; qq += 8) {
                int m = g_qlist[g.bin * QCAP + 16 * ch + qq];
                float cx = cen[((size_t)g.b * MM + m) * 2 + 0];
                float cy = cen[((size_t)g.b * MM + m) * 2 + 1];
                float sx = cx * scale, sy = cy * scale;
                float fix = floorf(sx), fiy = floorf(sy);
                float fx = sx - fix, fy = sy - fiy;
                int ox = (int)fix - 4 - g.px0;
                int oy = (int)fiy - 4 - g.py0;
                float wx1 = fx, wx0 = 1.f - fx, wy1 = fy, wy0 = 1.f - fy;
                const float* Dq = Ds + qq * DSTR;
                for (int e = lane; e < 81; e += 32) {
                    int i = e / 9, j = e - (e / 9) * 9;
                    int base = (oy + j) * g.pw + (ox + i);
                    float d00 = Dq[base],        d01 = Dq[base + 1];
                    float d10 = Dq[base + g.pw], d11 = Dq[base + g.pw + 1];
                    float val = wy0 * (wx0 * d00 + wx1 * d01)
                              + wy1 * (wx0 * d10 + wx1 * d11);
                    out[((size_t)g.b * 324 + g.lvl * 81 + e) * MM + m] = val;
                }
            }
            // next loop-top __syncthreads protects Ds before reuse
        }

        item = s_next;
        if (item >= NITEMS) return;
        g = get_geo(item);
        __syncthreads();                   // everyone read s_next
        if (tid == 0) s_next = next_item();
    }
}

// ---------------- launch ----------------------------------------------------
extern "C" void kernel_launch(void* const* d_in, const int* in_sizes, int n_in,
                              void* d_out, int out_size) {
    const float* f1  = (const float*)d_in[0];
    const float* f2  = (const float*)d_in[1];
    const float* cen = (const float*)d_in[2];
    float* out = (float*)d_out;

    size_t smem = (size_t)(2 * NPOS_MAX * PSTRH + 32 * PSTRH + 16 * DSTR) * sizeof(float);
    cudaFuncSetAttribute(corr_kernel, cudaFuncAttributeMaxDynamicSharedMemorySize,
                         (int)smem);

    transpose_kernel<<<dim3(HW * HW / 32, CC / 32, BB), dim3(32, 32)>>>(f2);
    pool_all_kernel<<<BB * 1344, 256>>>();
    hist_kernel<<<32, 256>>>(cen);
    corr_kernel<<<152, 256, smem>>>(f1, cen, out);
}

// round 11
// speedup vs baseline: 1.3466x; 1.3466x over previous
#include <cuda_runtime.h>
#include <math.h>

#define BB 2
#define MM 4096
#define CC 256
#define HW 64
#define NBINS 512
#define QCAP 96
#define NPOS_MAX 169
#define PSTRH 132                 // position stride in floats (gmem AND smem)
#define DSTR 172
#define PW0 73
#define TOTPOS 7924               // 73^2 + 41^2 + 25^2 + 17^2

// padded pyramid: [b][half][pos][132]
__device__ __align__(1024) float g_pyr2[BB * 2 * TOTPOS * PSTRH];
__device__ int g_cnt[NBINS];
__device__ int g_qlist[NBINS * QCAP];

__constant__ int c_lvl_base[4] = {0, 5329, 7010, 7635};
__constant__ int c_lvl_pw[4]   = {73, 41, 25, 17};

// ---------------- helpers ---------------------------------------------------
__device__ __forceinline__ void fma2(unsigned long long& d, unsigned long long a,
                                     unsigned long long b) {
    asm("fma.rn.f32x2 %0, %1, %2, %0;" : "+l"(d) : "l"(a), "l"(b));
}
__device__ __forceinline__ float unpack_sum(unsigned long long v) {
    return __uint_as_float((unsigned)v) + __uint_as_float((unsigned)(v >> 32));
}
__device__ __forceinline__ void bulkcp(unsigned dst, const void* src,
                                       unsigned bytes, unsigned mbar) {
    asm volatile("cp.async.bulk.shared::cluster.global.mbarrier::complete_tx::bytes "
                 "[%0], [%1], %2, [%3];" :: "r"(dst), "l"(src), "r"(bytes), "r"(mbar)
                 : "memory");
}
__device__ __forceinline__ void mbar_init(unsigned mbar, unsigned cnt) {
    asm volatile("mbarrier.init.shared.b64 [%0], %1;" :: "r"(mbar), "r"(cnt) : "memory");
}
__device__ __forceinline__ void mbar_expect(unsigned mbar, unsigned bytes) {
    asm volatile("mbarrier.arrive.expect_tx.shared.b64 _, [%0], %1;"
                 :: "r"(mbar), "r"(bytes) : "memory");
}
__device__ __forceinline__ void mbar_wait(unsigned mbar, unsigned parity) {
    unsigned done;
    asm volatile("{\n\t.reg .pred p;\n\t"
                 "mbarrier.try_wait.parity.shared.b64 p, [%1], %2;\n\t"
                 "selp.b32 %0, 1, 0, p;\n\t}" : "=r"(done) : "r"(mbar), "r"(parity)
                 : "memory");
    while (!done)
        asm volatile("{\n\t.reg .pred p;\n\t"
                     "mbarrier.try_wait.parity.shared.b64 p, [%1], %2, 0x989680;\n\t"
                     "selp.b32 %0, 1, 0, p;\n\t}" : "=r"(done)
                     : "r"(mbar), "r"(parity) : "memory");
}

// ---------------- kernel 1: transpose + zero counters -----------------------
__global__ void transpose_kernel(const float* __restrict__ f2) {
    __shared__ float tile[32][33];
    int b = blockIdx.z, p0 = blockIdx.x * 32, c0 = blockIdx.y * 32;
    int tx = threadIdx.x, ty = threadIdx.y;
    if (blockIdx.x == 0 && blockIdx.y == 0 && blockIdx.z == 0) {
        int t = ty * 32 + tx;
        if (t < NBINS) g_cnt[t] = 0;
    }
    tile[ty][tx] = f2[((size_t)b * CC + (c0 + ty)) * (HW * HW) + p0 + tx];
    __syncthreads();
    int p = p0 + ty, y = p >> 6, x = p & 63;
    int c = c0 + tx, h = c >> 7, cc = c & 127;
    int pos = (y + 4) * PW0 + (x + 4);
    g_pyr2[((size_t)(b * 2 + h) * TOTPOS + pos) * PSTRH + cc] = tile[tx][ty];
}

// ---------------- kernel 2: all pooled levels from L0 ------------------------
__global__ void pool_all_kernel() {
    int r = blockIdx.x;
    int b = r / 1344, t = r - b * 1344;
    int l, W, i;
    if (t < 1024)      { l = 1; W = 32; i = t; }
    else if (t < 1280) { l = 2; W = 16; i = t - 1024; }
    else               { l = 3; W = 8;  i = t - 1280; }
    int y = i / W, x = i - (i / W) * W;
    int S = 1 << l;
    int c = threadIdx.x;
    int h = c >> 7, cc = c & 127;
    const float* in = g_pyr2 + (size_t)(b * 2 + h) * TOTPOS * PSTRH + cc;
    float s = 0.f;
    for (int dy = 0; dy < S; dy++)
        for (int dx = 0; dx < S; dx++)
            s += in[(size_t)((y * S + dy + 4) * PW0 + (x * S + dx + 4)) * PSTRH];
    g_pyr2[((size_t)(b * 2 + h) * TOTPOS + c_lvl_base[l]
            + (y + 4) * c_lvl_pw[l] + (x + 4)) * PSTRH + cc] = s / (float)(S * S);
}

// ---------------- kernel 3: histogram + halo zeroing ------------------------
__global__ void hist_kernel(const float* __restrict__ cen) {
    int t = blockIdx.x * blockDim.x + threadIdx.x;

    for (int p = t; p < BB * 2 * TOTPOS; p += 32 * 256) {
        int pp = p % TOTPOS;
        int l = pp < 5329 ? 0 : (pp < 7010 ? 1 : (pp < 7635 ? 2 : 3));
        int pwl = c_lvl_pw[l];
        int r = pp - c_lvl_base[l];
        int y = r / pwl, x = r - (r / pwl) * pwl;
        int W = pwl - 9;
        if (x < 4 || x >= W + 4 || y < 4 || y >= W + 4) {
            float4* dst = (float4*)(g_pyr2 + (size_t)p * PSTRH);
            #pragma unroll 4
            for (int i = 0; i < PSTRH / 4; i++) dst[i] = make_float4(0.f, 0.f, 0.f, 0.f);
        }
    }

    if (t < BB * MM) {
        float cx = cen[2 * t], cy = cen[2 * t + 1];
        int bx = ((int)cx) >> 2;  bx = bx < 0 ? 0 : (bx > 15 ? 15 : bx);
        int by = ((int)cy) >> 2;  by = by < 0 ? 0 : (by > 15 ? 15 : by);
        int b = t / MM, m = t - b * MM;
        int bin = (b << 8) | (by << 4) | bx;
        int pos = atomicAdd(&g_cnt[bin], 1);
        if (pos < QCAP) g_qlist[bin * QCAP + pos] = m;
    }
}

// ---------------- GEMM inner loop: 4q x 6 strips (48 pos) per warp ----------
template <int NQI>
__device__ __forceinline__ void gemm_half(const float* __restrict__ As,
                                          const float* __restrict__ Ps,
                                          int qsel, const int* poff,
                                          unsigned long long acc[4][6]) {
    #pragma unroll 2
    for (int c = 0; c < 128; c += 4) {
        ulonglong2 a[NQI], p[6];
        #pragma unroll
        for (int qi = 0; qi < NQI; qi++)
            a[qi] = *(const ulonglong2*)&As[(qsel + 4 * qi) * PSTRH + c];
        #pragma unroll
        for (int pi = 0; pi < 6; pi++)
            p[pi] = *(const ulonglong2*)&Ps[poff[pi] + c];
        #pragma unroll
        for (int qi = 0; qi < NQI; qi++)
            #pragma unroll
            for (int pi = 0; pi < 6; pi++) {
                fma2(acc[qi][pi], a[qi].x, p[pi].x);
                fma2(acc[qi][pi], a[qi].y, p[pi].y);
            }
    }
}

__global__ __launch_bounds__(256, 2) void corr_kernel(const float* __restrict__ f1,
                                                      const float* __restrict__ cen,
                                                      float* __restrict__ out) {
    extern __shared__ float sm[];
    float* Ps = sm;                           // 169*132
    float* As = sm + NPOS_MAX * PSTRH;        // 16*132
    float* Ds = As + 16 * PSTRH;              // 16*172
    __shared__ __align__(8) unsigned long long mbar_s;

    int blk = blockIdx.x;
    int lvl = blk & 3, bin = blk >> 2;
    int b = bin >> 8, by = (bin >> 4) & 15, bx = bin & 15;
    int nq = g_cnt[bin]; if (nq > QCAP) nq = QCAP;
    if (nq == 0) return;

    int ixmin = (4 * bx) >> lvl, ixmax = (4 * bx + 3) >> lvl;
    int iymin = (4 * by) >> lvl, iymax = (4 * by + 3) >> lvl;
    int px0 = ixmin - 4, py0 = iymin - 4;
    int pw = ixmax - ixmin + 10, ph = iymax - iymin + 10;
    int Npos = pw * ph;
    int pwp = c_lvl_pw[lvl];

    int tid = threadIdx.x, lane = tid & 31, w = tid >> 5;
    int qsel = lane >> 3, psel = lane & 7;
    int wbase = w * 48;                       // 48 positions per warp
    bool act = wbase < Npos;
    float scale = 1.0f / (float)(1 << lvl);

    unsigned Ps_b = (unsigned)__cvta_generic_to_shared(Ps);
    unsigned As_b = (unsigned)__cvta_generic_to_shared(As);
    unsigned mbar = (unsigned)__cvta_generic_to_shared(&mbar_s);

    if (tid == 0) mbar_init(mbar, 1);
    __syncthreads();
    unsigned par = 0;

    int poff[6];
    #pragma unroll
    for (int pi = 0; pi < 6; pi++) {
        int p = wbase + psel + 8 * pi;
        poff[pi] = ((p < Npos) ? p : (Npos - 1)) * PSTRH;
    }

    for (int q0 = 0; q0 < nq; q0 += 16) {
        int qcnt = nq - q0; if (qcnt > 16) qcnt = 16;
        int nqi = (qcnt + 3) >> 2;            // 1..4, uniform across warps

        unsigned long long acc[4][6];
        #pragma unroll
        for (int qi = 0; qi < 4; qi++)
            #pragma unroll
            for (int pi = 0; pi < 6; pi++) acc[qi][pi] = 0ull;

        for (int h = 0; h < 2; h++) {
            __syncthreads();   // previous phase's smem fully consumed
            if (tid == 0)
                mbar_expect(mbar, (unsigned)Npos * (PSTRH * 4u) + 16u * 512u);

            const float* pbase = g_pyr2
                + ((size_t)(b * 2 + h) * TOTPOS + c_lvl_base[lvl]
                   + (size_t)(py0 + 4) * pwp + (px0 + 4)) * PSTRH;
            int nops = Npos + 16;
            for (int i = tid; i < nops; i += 256) {
                if (i < Npos) {
                    int ly = i / pw, lx = i - (i / pw) * pw;
                    bulkcp(Ps_b + (unsigned)(i * PSTRH) * 4u,
                           pbase + ((size_t)ly * pwp + lx) * PSTRH, PSTRH * 4u, mbar);
                } else {
                    int qq = i - Npos;
                    int qv = (qq < qcnt) ? qq : 0;
                    int m = g_qlist[bin * QCAP + q0 + qv];
                    bulkcp(As_b + (unsigned)(qq * PSTRH) * 4u,
                           f1 + ((size_t)b * MM + m) * CC + h * 128, 512u, mbar);
                }
            }
            mbar_wait(mbar, par);
            par ^= 1;

            if (act) {
                switch (nqi) {
                    case 4: gemm_half<4>(As, Ps, qsel, poff, acc); break;
                    case 3: gemm_half<3>(As, Ps, qsel, poff, acc); break;
                    case 2: gemm_half<2>(As, Ps, qsel, poff, acc); break;
                    default: gemm_half<1>(As, Ps, qsel, poff, acc); break;
                }
            }
        }

        // ---- write D -------------------------------------------------------
        if (act) {
            #pragma unroll
            for (int pi = 0; pi < 6; pi++) {
                int p = wbase + psel + 8 * pi;
                if (p < Npos) {
                    #pragma unroll
                    for (int qi = 0; qi < 4; qi++)
                        Ds[(qsel + 4 * qi) * DSTR + p] = unpack_sum(acc[qi][pi]);
                }
            }
        }
        __syncthreads();

        // ---- bilinear epilogue: warp per query -----------------------------
        for (int qq = w; qq < qcnt; qq += 8) {
            int m = g_qlist[bin * QCAP + q0 + qq];
            float cx = cen[((size_t)b * MM + m) * 2 + 0];
            float cy = cen[((size_t)b * MM + m) * 2 + 1];
            float sx = cx * scale, sy = cy * scale;
            float fix = floorf(sx), fiy = floorf(sy);
            float fx = sx - fix, fy = sy - fiy;
            int ox = (int)fix - 4 - px0;
            int oy = (int)fiy - 4 - py0;
            float wx1 = fx, wx0 = 1.f - fx, wy1 = fy, wy0 = 1.f - fy;
            const float* Dq = Ds + qq * DSTR;
            for (int e = lane; e < 81; e += 32) {
                int i = e / 9, j = e - (e / 9) * 9;
                int base = (oy + j) * pw + (ox + i);
                float d00 = Dq[base],      d01 = Dq[base + 1];
                float d10 = Dq[base + pw], d11 = Dq[base + pw + 1];
                float val = wy0 * (wx0 * d00 + wx1 * d01)
                          + wy1 * (wx0 * d10 + wx1 * d11);
                out[((size_t)b * 324 + lvl * 81 + e) * MM + m] = val;
            }
        }
    }
}

// ---------------- launch ----------------------------------------------------
extern "C" void kernel_launch(void* const* d_in, const int* in_sizes, int n_in,
                              void* d_out, int out_size) {
    const float* f1  = (const float*)d_in[0];
    const float* f2  = (const float*)d_in[1];
    const float* cen = (const float*)d_in[2];
    float* out = (float*)d_out;

    size_t smem = (size_t)(NPOS_MAX * PSTRH + 16 * PSTRH + 16 * DSTR) * sizeof(float);
    cudaFuncSetAttribute(corr_kernel, cudaFuncAttributeMaxDynamicSharedMemorySize,
                         (int)smem);

    transpose_kernel<<<dim3(HW * HW / 32, CC / 32, BB), dim3(32, 32)>>>(f2);
    pool_all_kernel<<<BB * 1344, 256>>>();
    hist_kernel<<<32, 256>>>(cen);
    corr_kernel<<<NBINS * 4, 256, smem>>>(f1, cen, out);
}

// round 12
// speedup vs baseline: 1.4819x; 1.1004x over previous
#include <cuda_runtime.h>
#include <math.h>

#define BB 2
#define MM 4096
#define CC 256
#define HW 64
#define NBINS 512
#define QCAP 96
#define NPOS_MAX 169
#define PSTRH 132                 // position stride in floats (gmem AND smem)
#define DSTR 172
#define PW0 73
#define TOTPOS 7924               // 73^2 + 41^2 + 25^2 + 17^2

// padded pyramid: [b][half][pos][132]
__device__ __align__(1024) float g_pyr2[BB * 2 * TOTPOS * PSTRH];
__device__ int g_cnt[NBINS];
__device__ int g_qlist[NBINS * QCAP];

__constant__ int c_lvl_base[4] = {0, 5329, 7010, 7635};
__constant__ int c_lvl_pw[4]   = {73, 41, 25, 17};

// ---------------- helpers ---------------------------------------------------
__device__ __forceinline__ void fma2(unsigned long long& d, unsigned long long a,
                                     unsigned long long b) {
    asm("fma.rn.f32x2 %0, %1, %2, %0;" : "+l"(d) : "l"(a), "l"(b));
}
__device__ __forceinline__ float unpack_sum(unsigned long long v) {
    return __uint_as_float((unsigned)v) + __uint_as_float((unsigned)(v >> 32));
}
__device__ __forceinline__ void bulkcp(unsigned dst, const void* src,
                                       unsigned bytes, unsigned mbar) {
    asm volatile("cp.async.bulk.shared::cluster.global.mbarrier::complete_tx::bytes "
                 "[%0], [%1], %2, [%3];" :: "r"(dst), "l"(src), "r"(bytes), "r"(mbar)
                 : "memory");
}
__device__ __forceinline__ void mbar_init(unsigned mbar, unsigned cnt) {
    asm volatile("mbarrier.init.shared.b64 [%0], %1;" :: "r"(mbar), "r"(cnt) : "memory");
}
__device__ __forceinline__ void mbar_expect(unsigned mbar, unsigned bytes) {
    asm volatile("mbarrier.arrive.expect_tx.shared.b64 _, [%0], %1;"
                 :: "r"(mbar), "r"(bytes) : "memory");
}
__device__ __forceinline__ void mbar_wait(unsigned mbar, unsigned parity) {
    unsigned done;
    asm volatile("{\n\t.reg .pred p;\n\t"
                 "mbarrier.try_wait.parity.shared.b64 p, [%1], %2;\n\t"
                 "selp.b32 %0, 1, 0, p;\n\t}" : "=r"(done) : "r"(mbar), "r"(parity)
                 : "memory");
    while (!done)
        asm volatile("{\n\t.reg .pred p;\n\t"
                     "mbarrier.try_wait.parity.shared.b64 p, [%1], %2, 0x989680;\n\t"
                     "selp.b32 %0, 1, 0, p;\n\t}" : "=r"(done)
                     : "r"(mbar), "r"(parity) : "memory");
}

// ---------------- kernel 1: transpose + zero counters -----------------------
__global__ void transpose_kernel(const float* __restrict__ f2) {
    __shared__ float tile[32][33];
    int b = blockIdx.z, p0 = blockIdx.x * 32, c0 = blockIdx.y * 32;
    int tx = threadIdx.x, ty = threadIdx.y;
    if (blockIdx.x == 0 && blockIdx.y == 0 && blockIdx.z == 0) {
        int t = ty * 32 + tx;
        if (t < NBINS) g_cnt[t] = 0;
    }
    tile[ty][tx] = f2[((size_t)b * CC + (c0 + ty)) * (HW * HW) + p0 + tx];
    __syncthreads();
    int p = p0 + ty, y = p >> 6, x = p & 63;
    int c = c0 + tx, h = c >> 7, cc = c & 127;
    int pos = (y + 4) * PW0 + (x + 4);
    g_pyr2[((size_t)(b * 2 + h) * TOTPOS + pos) * PSTRH + cc] = tile[tx][ty];
}

// ---------------- kernel 2: all pooled levels from L0 ------------------------
__global__ void pool_all_kernel() {
    int r = blockIdx.x;
    int b = r / 1344, t = r - b * 1344;
    int l, W, i;
    if (t < 1024)      { l = 1; W = 32; i = t; }
    else if (t < 1280) { l = 2; W = 16; i = t - 1024; }
    else               { l = 3; W = 8;  i = t - 1280; }
    int y = i / W, x = i - (i / W) * W;
    int S = 1 << l;
    int c = threadIdx.x;
    int h = c >> 7, cc = c & 127;
    const float* in = g_pyr2 + (size_t)(b * 2 + h) * TOTPOS * PSTRH + cc;
    float s = 0.f;
    for (int dy = 0; dy < S; dy++)
        for (int dx = 0; dx < S; dx++)
            s += in[(size_t)((y * S + dy + 4) * PW0 + (x * S + dx + 4)) * PSTRH];
    g_pyr2[((size_t)(b * 2 + h) * TOTPOS + c_lvl_base[l]
            + (y + 4) * c_lvl_pw[l] + (x + 4)) * PSTRH + cc] = s / (float)(S * S);
}

// ---------------- kernel 3: histogram + halo zeroing ------------------------
__global__ void hist_kernel(const float* __restrict__ cen) {
    int t = blockIdx.x * blockDim.x + threadIdx.x;

    for (int p = t; p < BB * 2 * TOTPOS; p += 32 * 256) {
        int pp = p % TOTPOS;
        int l = pp < 5329 ? 0 : (pp < 7010 ? 1 : (pp < 7635 ? 2 : 3));
        int pwl = c_lvl_pw[l];
        int r = pp - c_lvl_base[l];
        int y = r / pwl, x = r - (r / pwl) * pwl;
        int W = pwl - 9;
        if (x < 4 || x >= W + 4 || y < 4 || y >= W + 4) {
            float4* dst = (float4*)(g_pyr2 + (size_t)p * PSTRH);
            #pragma unroll 4
            for (int i = 0; i < PSTRH / 4; i++) dst[i] = make_float4(0.f, 0.f, 0.f, 0.f);
        }
    }

    if (t < BB * MM) {
        float cx = cen[2 * t], cy = cen[2 * t + 1];
        int bx = ((int)cx) >> 2;  bx = bx < 0 ? 0 : (bx > 15 ? 15 : bx);
        int by = ((int)cy) >> 2;  by = by < 0 ? 0 : (by > 15 ? 15 : by);
        int b = t / MM, m = t - b * MM;
        int bin = (b << 8) | (by << 4) | bx;
        int pos = atomicAdd(&g_cnt[bin], 1);
        if (pos < QCAP) g_qlist[bin * QCAP + pos] = m;
    }
}

// ---------------- GEMM inner loop: 4q x 4 strips (32 pos) per warp ----------
template <int NQI>
__device__ __forceinline__ void gemm_half(const float* __restrict__ As,
                                          const float* __restrict__ Ps,
                                          int qsel, const int* poff,
                                          unsigned long long acc[4][4]) {
    #pragma unroll 4
    for (int c = 0; c < 128; c += 4) {
        ulonglong2 a[NQI], p[4];
        #pragma unroll
        for (int qi = 0; qi < NQI; qi++)
            a[qi] = *(const ulonglong2*)&As[(qsel + 4 * qi) * PSTRH + c];
        #pragma unroll
        for (int pi = 0; pi < 4; pi++)
            p[pi] = *(const ulonglong2*)&Ps[poff[pi] + c];
        #pragma unroll
        for (int qi = 0; qi < NQI; qi++)
            #pragma unroll
            for (int pi = 0; pi < 4; pi++) {
                fma2(acc[qi][pi], a[qi].x, p[pi].x);
                fma2(acc[qi][pi], a[qi].y, p[pi].y);
            }
    }
}

__global__ __launch_bounds__(256, 2) void corr_kernel(const float* __restrict__ f1,
                                                      const float* __restrict__ cen,
                                                      float* __restrict__ out) {
    extern __shared__ float sm[];
    float* Ps = sm;                           // 169*132
    float* As = sm + NPOS_MAX * PSTRH;        // 16*132
    float* Ds = As + 16 * PSTRH;              // 16*172
    __shared__ __align__(8) unsigned long long mbar_s;

    int blk = blockIdx.x;
    int lvl = blk >> 9, bin = blk & 511;      // LPT: all L0 items first
    int b = bin >> 8, by = (bin >> 4) & 15, bx = bin & 15;
    int nq = g_cnt[bin]; if (nq > QCAP) nq = QCAP;
    if (nq == 0) return;

    int ixmin = (4 * bx) >> lvl, ixmax = (4 * bx + 3) >> lvl;
    int iymin = (4 * by) >> lvl, iymax = (4 * by + 3) >> lvl;
    int px0 = ixmin - 4, py0 = iymin - 4;
    int pw = ixmax - ixmin + 10, ph = iymax - iymin + 10;
    int Npos = pw * ph;
    int pwp = c_lvl_pw[lvl];

    int tid = threadIdx.x, lane = tid & 31, w = tid >> 5;
    int qsel = lane >> 3, psel = lane & 7;
    int wbase = w * 32;
    bool act = wbase < Npos;
    float scale = 1.0f / (float)(1 << lvl);

    unsigned Ps_b = (unsigned)__cvta_generic_to_shared(Ps);
    unsigned As_b = (unsigned)__cvta_generic_to_shared(As);
    unsigned mbar = (unsigned)__cvta_generic_to_shared(&mbar_s);

    if (tid == 0) mbar_init(mbar, 1);
    __syncthreads();
    unsigned par = 0;

    int poff[4];
    #pragma unroll
    for (int pi = 0; pi < 4; pi++) {
        int p = wbase + psel + 8 * pi;
        poff[pi] = ((p < Npos) ? p : (Npos - 1)) * PSTRH;
    }

    for (int q0 = 0; q0 < nq; q0 += 16) {
        int qcnt = nq - q0; if (qcnt > 16) qcnt = 16;
        int nqi = (qcnt + 3) >> 2;            // 1..4, uniform across warps

        unsigned long long acc[4][4];
        #pragma unroll
        for (int qi = 0; qi < 4; qi++)
            #pragma unroll
            for (int pi = 0; pi < 4; pi++) acc[qi][pi] = 0ull;

        for (int h = 0; h < 2; h++) {
            __syncthreads();   // previous phase's smem fully consumed
            if (tid == 0)
                mbar_expect(mbar, (unsigned)Npos * (PSTRH * 4u)
                                  + (unsigned)qcnt * 512u);

            const float* pbase = g_pyr2
                + ((size_t)(b * 2 + h) * TOTPOS + c_lvl_base[lvl]
                   + (size_t)(py0 + 4) * pwp + (px0 + 4)) * PSTRH;
            int nops = Npos + qcnt;
            for (int i = tid; i < nops; i += 256) {
                if (i < Npos) {
                    int ly = i / pw, lx = i - (i / pw) * pw;
                    bulkcp(Ps_b + (unsigned)(i * PSTRH) * 4u,
                           pbase + ((size_t)ly * pwp + lx) * PSTRH, PSTRH * 4u, mbar);
                } else {
                    int qq = i - Npos;
                    int m = g_qlist[bin * QCAP + q0 + qq];
                    bulkcp(As_b + (unsigned)(qq * PSTRH) * 4u,
                           f1 + ((size_t)b * MM + m) * CC + h * 128, 512u, mbar);
                }
            }
            mbar_wait(mbar, par);
            par ^= 1;

            if (act) {
                switch (nqi) {
                    case 4: gemm_half<4>(As, Ps, qsel, poff, acc); break;
                    case 3: gemm_half<3>(As, Ps, qsel, poff, acc); break;
                    case 2: gemm_half<2>(As, Ps, qsel, poff, acc); break;
                    default: gemm_half<1>(As, Ps, qsel, poff, acc); break;
                }
            }
        }

        // ---- write D -------------------------------------------------------
        if (act) {
            #pragma unroll
            for (int pi = 0; pi < 4; pi++) {
                int p = wbase + psel + 8 * pi;
                if (p < Npos) {
                    #pragma unroll
                    for (int qi = 0; qi < 4; qi++)
                        Ds[(qsel + 4 * qi) * DSTR + p] = unpack_sum(acc[qi][pi]);
                }
            }
        }
        __syncthreads();

        // ---- bilinear epilogue: warp per query -----------------------------
        for (int qq = w; qq < qcnt; qq += 8) {
            int m = g_qlist[bin * QCAP + q0 + qq];
            float cx = cen[((size_t)b * MM + m) * 2 + 0];
            float cy = cen[((size_t)b * MM + m) * 2 + 1];
            float sx = cx * scale, sy = cy * scale;
            float fix = floorf(sx), fiy = floorf(sy);
            float fx = sx - fix, fy = sy - fiy;
            int ox = (int)fix - 4 - px0;
            int oy = (int)fiy - 4 - py0;
            float wx1 = fx, wx0 = 1.f - fx, wy1 = fy, wy0 = 1.f - fy;
            const float* Dq = Ds + qq * DSTR;
            for (int e = lane; e < 81; e += 32) {
                int i = e / 9, j = e - (e / 9) * 9;
                int base = (oy + j) * pw + (ox + i);
                float d00 = Dq[base],      d01 = Dq[base + 1];
                float d10 = Dq[base + pw], d11 = Dq[base + pw + 1];
                float val = wy0 * (wx0 * d00 + wx1 * d01)
                          + wy1 * (wx0 * d10 + wx1 * d11);
                out[((size_t)b * 324 + lvl * 81 + e) * MM + m] = val;
            }
        }
    }
}

// ---------------- launch ----------------------------------------------------
extern "C" void kernel_launch(void* const* d_in, const int* in_sizes, int n_in,
                              void* d_out, int out_size) {
    const float* f1  = (const float*)d_in[0];
    const float* f2  = (const float*)d_in[1];
    const float* cen = (const float*)d_in[2];
    float* out = (float*)d_out;

    size_t smem = (size_t)(NPOS_MAX * PSTRH + 16 * PSTRH + 16 * DSTR) * sizeof(float);
    cudaFuncSetAttribute(corr_kernel, cudaFuncAttributeMaxDynamicSharedMemorySize,
                         (int)smem);

    transpose_kernel<<<dim3(HW * HW / 32, CC / 32, BB), dim3(32, 32)>>>(f2);
    pool_all_kernel<<<BB * 1344, 256>>>();
    hist_kernel<<<32, 256>>>(cen);
    corr_kernel<<<NBINS * 4, 256, smem>>>(f1, cen, out);
}

// round 13
// speedup vs baseline: 1.4847x; 1.0019x over previous
#include <cuda_runtime.h>
#include <math.h>

#define BB 2
#define MM 4096
#define CC 256
#define HW 64
#define NBINS 512
#define QCAP 96
#define NPOS_MAX 169
#define PSTRH 132                 // position stride in floats (gmem AND smem)
#define DSTR 172
#define PW0 73
#define TOTPOS 7924               // 73^2 + 41^2 + 25^2 + 17^2

// padded pyramid: [b][half][pos][132]
__device__ __align__(1024) float g_pyr2[BB * 2 * TOTPOS * PSTRH];
__device__ int g_cnt[NBINS];
__device__ int g_qlist[NBINS * QCAP];
__device__ float g_outT[BB * MM * 324];   // [b][m][324] coalesced scratch

__constant__ int c_lvl_base[4] = {0, 5329, 7010, 7635};
__constant__ int c_lvl_pw[4]   = {73, 41, 25, 17};

// ---------------- helpers ---------------------------------------------------
__device__ __forceinline__ void fma2(unsigned long long& d, unsigned long long a,
                                     unsigned long long b) {
    asm("fma.rn.f32x2 %0, %1, %2, %0;" : "+l"(d) : "l"(a), "l"(b));
}
__device__ __forceinline__ float unpack_sum(unsigned long long v) {
    return __uint_as_float((unsigned)v) + __uint_as_float((unsigned)(v >> 32));
}
__device__ __forceinline__ void bulkcp(unsigned dst, const void* src,
                                       unsigned bytes, unsigned mbar) {
    asm volatile("cp.async.bulk.shared::cluster.global.mbarrier::complete_tx::bytes "
                 "[%0], [%1], %2, [%3];" :: "r"(dst), "l"(src), "r"(bytes), "r"(mbar)
                 : "memory");
}
__device__ __forceinline__ void mbar_init(unsigned mbar, unsigned cnt) {
    asm volatile("mbarrier.init.shared.b64 [%0], %1;" :: "r"(mbar), "r"(cnt) : "memory");
}
__device__ __forceinline__ void mbar_expect(unsigned mbar, unsigned bytes) {
    asm volatile("mbarrier.arrive.expect_tx.shared.b64 _, [%0], %1;"
                 :: "r"(mbar), "r"(bytes) : "memory");
}
__device__ __forceinline__ void mbar_wait(unsigned mbar, unsigned parity) {
    unsigned done;
    asm volatile("{\n\t.reg .pred p;\n\t"
                 "mbarrier.try_wait.parity.shared.b64 p, [%1], %2;\n\t"
                 "selp.b32 %0, 1, 0, p;\n\t}" : "=r"(done) : "r"(mbar), "r"(parity)
                 : "memory");
    while (!done)
        asm volatile("{\n\t.reg .pred p;\n\t"
                     "mbarrier.try_wait.parity.shared.b64 p, [%1], %2, 0x989680;\n\t"
                     "selp.b32 %0, 1, 0, p;\n\t}" : "=r"(done)
                     : "r"(mbar), "r"(parity) : "memory");
}

// ---------------- kernel 1: transpose + zero counters -----------------------
__global__ void transpose_kernel(const float* __restrict__ f2) {
    __shared__ float tile[32][33];
    int b = blockIdx.z, p0 = blockIdx.x * 32, c0 = blockIdx.y * 32;
    int tx = threadIdx.x, ty = threadIdx.y;
    if (blockIdx.x == 0 && blockIdx.y == 0 && blockIdx.z == 0) {
        int t = ty * 32 + tx;
        if (t < NBINS) g_cnt[t] = 0;
    }
    tile[ty][tx] = f2[((size_t)b * CC + (c0 + ty)) * (HW * HW) + p0 + tx];
    __syncthreads();
    int p = p0 + ty, y = p >> 6, x = p & 63;
    int c = c0 + tx, h = c >> 7, cc = c & 127;
    int pos = (y + 4) * PW0 + (x + 4);
    g_pyr2[((size_t)(b * 2 + h) * TOTPOS + pos) * PSTRH + cc] = tile[tx][ty];
}

// ---------------- kernel 2: all pooled levels from L0 ------------------------
__global__ void pool_all_kernel() {
    int r = blockIdx.x;
    int b = r / 1344, t = r - b * 1344;
    int l, W, i;
    if (t < 1024)      { l = 1; W = 32; i = t; }
    else if (t < 1280) { l = 2; W = 16; i = t - 1024; }
    else               { l = 3; W = 8;  i = t - 1280; }
    int y = i / W, x = i - (i / W) * W;
    int S = 1 << l;
    int c = threadIdx.x;
    int h = c >> 7, cc = c & 127;
    const float* in = g_pyr2 + (size_t)(b * 2 + h) * TOTPOS * PSTRH + cc;
    float s = 0.f;
    for (int dy = 0; dy < S; dy++)
        for (int dx = 0; dx < S; dx++)
            s += in[(size_t)((y * S + dy + 4) * PW0 + (x * S + dx + 4)) * PSTRH];
    g_pyr2[((size_t)(b * 2 + h) * TOTPOS + c_lvl_base[l]
            + (y + 4) * c_lvl_pw[l] + (x + 4)) * PSTRH + cc] = s / (float)(S * S);
}

// ---------------- kernel 3: histogram + halo zeroing ------------------------
__global__ void hist_kernel(const float* __restrict__ cen) {
    int t = blockIdx.x * blockDim.x + threadIdx.x;

    for (int p = t; p < BB * 2 * TOTPOS; p += 32 * 256) {
        int pp = p % TOTPOS;
        int l = pp < 5329 ? 0 : (pp < 7010 ? 1 : (pp < 7635 ? 2 : 3));
        int pwl = c_lvl_pw[l];
        int r = pp - c_lvl_base[l];
        int y = r / pwl, x = r - (r / pwl) * pwl;
        int W = pwl - 9;
        if (x < 4 || x >= W + 4 || y < 4 || y >= W + 4) {
            float4* dst = (float4*)(g_pyr2 + (size_t)p * PSTRH);
            #pragma unroll 4
            for (int i = 0; i < PSTRH / 4; i++) dst[i] = make_float4(0.f, 0.f, 0.f, 0.f);
        }
    }

    if (t < BB * MM) {
        float cx = cen[2 * t], cy = cen[2 * t + 1];
        int bx = ((int)cx) >> 2;  bx = bx < 0 ? 0 : (bx > 15 ? 15 : bx);
        int by = ((int)cy) >> 2;  by = by < 0 ? 0 : (by > 15 ? 15 : by);
        int b = t / MM, m = t - b * MM;
        int bin = (b << 8) | (by << 4) | bx;
        int pos = atomicAdd(&g_cnt[bin], 1);
        if (pos < QCAP) g_qlist[bin * QCAP + pos] = m;
    }
}

// ---------------- GEMM inner loop: 4q x 4 strips (32 pos) per warp ----------
template <int NQI>
__device__ __forceinline__ void gemm_half(const float* __restrict__ As,
                                          const float* __restrict__ Ps,
                                          int qsel, const int* poff,
                                          unsigned long long acc[4][4]) {
    #pragma unroll 2
    for (int c = 0; c < 128; c += 4) {
        ulonglong2 a[NQI], p[4];
        #pragma unroll
        for (int qi = 0; qi < NQI; qi++)
            a[qi] = *(const ulonglong2*)&As[(qsel + 4 * qi) * PSTRH + c];
        #pragma unroll
        for (int pi = 0; pi < 4; pi++)
            p[pi] = *(const ulonglong2*)&Ps[poff[pi] + c];
        #pragma unroll
        for (int qi = 0; qi < NQI; qi++)
            #pragma unroll
            for (int pi = 0; pi < 4; pi++) {
                fma2(acc[qi][pi], a[qi].x, p[pi].x);
                fma2(acc[qi][pi], a[qi].y, p[pi].y);
            }
    }
}

__global__ __launch_bounds__(256, 2) void corr_kernel(const float* __restrict__ f1,
                                                      const float* __restrict__ cen) {
    extern __shared__ float sm[];
    float* Ps = sm;                           // 169*132
    float* As = sm + NPOS_MAX * PSTRH;        // 16*132
    float* Ds = As + 16 * PSTRH;              // 16*172
    __shared__ __align__(8) unsigned long long mbar_s;

    int blk = blockIdx.x;
    int lvl = blk >> 9, bin = blk & 511;      // LPT: all L0 items first
    int b = bin >> 8, by = (bin >> 4) & 15, bx = bin & 15;
    int nq = g_cnt[bin]; if (nq > QCAP) nq = QCAP;
    if (nq == 0) return;

    int ixmin = (4 * bx) >> lvl, ixmax = (4 * bx + 3) >> lvl;
    int iymin = (4 * by) >> lvl, iymax = (4 * by + 3) >> lvl;
    int px0 = ixmin - 4, py0 = iymin - 4;
    int pw = ixmax - ixmin + 10, ph = iymax - iymin + 10;
    int Npos = pw * ph;
    int pwp = c_lvl_pw[lvl];

    int tid = threadIdx.x, lane = tid & 31, w = tid >> 5;
    int qsel = lane >> 3, psel = lane & 7;
    int wbase = w * 32;
    bool act = wbase < Npos;
    float scale = 1.0f / (float)(1 << lvl);

    unsigned Ps_b = (unsigned)__cvta_generic_to_shared(Ps);
    unsigned As_b = (unsigned)__cvta_generic_to_shared(As);
    unsigned mbar = (unsigned)__cvta_generic_to_shared(&mbar_s);

    if (tid == 0) mbar_init(mbar, 1);
    __syncthreads();
    unsigned par = 0;

    int poff[4];
    #pragma unroll
    for (int pi = 0; pi < 4; pi++) {
        int p = wbase + psel + 8 * pi;
        poff[pi] = ((p < Npos) ? p : (Npos - 1)) * PSTRH;
    }

    unsigned rowB = (unsigned)(pw * PSTRH * 4);   // bytes per contiguous patch row

    for (int q0 = 0; q0 < nq; q0 += 16) {
        int qcnt = nq - q0; if (qcnt > 16) qcnt = 16;
        int nqi = (qcnt + 3) >> 2;            // 1..4, uniform across warps

        unsigned long long acc[4][4];
        #pragma unroll
        for (int qi = 0; qi < 4; qi++)
            #pragma unroll
            for (int pi = 0; pi < 4; pi++) acc[qi][pi] = 0ull;

        for (int h = 0; h < 2; h++) {
            __syncthreads();   // previous phase's smem fully consumed
            if (tid == 0)
                mbar_expect(mbar, (unsigned)Npos * (PSTRH * 4u)
                                  + (unsigned)qcnt * 512u);

            const float* pbase = g_pyr2
                + ((size_t)(b * 2 + h) * TOTPOS + c_lvl_base[lvl]
                   + (size_t)(py0 + 4) * pwp + (px0 + 4)) * PSTRH;
            // row-granular patch staging: ph ops of pw*528 B (contiguous both sides)
            if (tid < ph) {
                bulkcp(Ps_b + (unsigned)(tid * pw * PSTRH) * 4u,
                       pbase + (size_t)tid * pwp * PSTRH, rowB, mbar);
            } else if (tid < ph + qcnt) {
                int qq = tid - ph;
                int m = g_qlist[bin * QCAP + q0 + qq];
                bulkcp(As_b + (unsigned)(qq * PSTRH) * 4u,
                       f1 + ((size_t)b * MM + m) * CC + h * 128, 512u, mbar);
            }
            mbar_wait(mbar, par);
            par ^= 1;

            if (act) {
                switch (nqi) {
                    case 4: gemm_half<4>(As, Ps, qsel, poff, acc); break;
                    case 3: gemm_half<3>(As, Ps, qsel, poff, acc); break;
                    case 2: gemm_half<2>(As, Ps, qsel, poff, acc); break;
                    default: gemm_half<1>(As, Ps, qsel, poff, acc); break;
                }
            }
        }

        // ---- write D -------------------------------------------------------
        if (act) {
            #pragma unroll
            for (int pi = 0; pi < 4; pi++) {
                int p = wbase + psel + 8 * pi;
                if (p < Npos) {
                    #pragma unroll
                    for (int qi = 0; qi < 4; qi++)
                        Ds[(qsel + 4 * qi) * DSTR + p] = unpack_sum(acc[qi][pi]);
                }
            }
        }
        __syncthreads();

        // ---- bilinear epilogue: warp per query, coalesced scratch writes ---
        for (int qq = w; qq < qcnt; qq += 8) {
            int m = g_qlist[bin * QCAP + q0 + qq];
            float cx = cen[((size_t)b * MM + m) * 2 + 0];
            float cy = cen[((size_t)b * MM + m) * 2 + 1];
            float sx = cx * scale, sy = cy * scale;
            float fix = floorf(sx), fiy = floorf(sy);
            float fx = sx - fix, fy = sy - fiy;
            int ox = (int)fix - 4 - px0;
            int oy = (int)fiy - 4 - py0;
            float wx1 = fx, wx0 = 1.f - fx, wy1 = fy, wy0 = 1.f - fy;
            const float* Dq = Ds + qq * DSTR;
            float* dst = g_outT + ((size_t)b * MM + m) * 324 + lvl * 81;
            for (int e = lane; e < 81; e += 32) {
                int i = e / 9, j = e - (e / 9) * 9;
                int base = (oy + j) * pw + (ox + i);
                float d00 = Dq[base],      d01 = Dq[base + 1];
                float d10 = Dq[base + pw], d11 = Dq[base + pw + 1];
                dst[e] = wy0 * (wx0 * d00 + wx1 * d01)
                       + wy1 * (wx0 * d10 + wx1 * d11);
            }
        }
    }
}

// ---------------- kernel 5: transpose scratch -> out (B, 324, M) ------------
__global__ void out_transpose_kernel(float* __restrict__ out) {
    __shared__ float tile[32][33];
    int b = blockIdx.z;
    int m0 = blockIdx.x * 32, e0 = blockIdx.y * 32;
    int tx = threadIdx.x, ty = threadIdx.y;
    int e = e0 + ty;
    if (e < 324)
        tile[tx][ty] = g_outT[((size_t)b * MM + m0 + tx) * 324 + e];
    __syncthreads();
    // wait — need coalesced read: lanes (tx) vary fastest over the 324-dim.
    // Reload pattern below is the coalesced one; the above keeps symmetry.
    __syncthreads();
    int er = e0 + ty;
    if (er < 324)
        out[((size_t)b * 324 + er) * MM + m0 + tx] = tile[tx][ty];
}

// ---------------- launch ----------------------------------------------------
extern "C" void kernel_launch(void* const* d_in, const int* in_sizes, int n_in,
                              void* d_out, int out_size) {
    const float* f1  = (const float*)d_in[0];
    const float* f2  = (const float*)d_in[1];
    const float* cen = (const float*)d_in[2];
    float* out = (float*)d_out;

    size_t smem = (size_t)(NPOS_MAX * PSTRH + 16 * PSTRH + 16 * DSTR) * sizeof(float);
    cudaFuncSetAttribute(corr_kernel, cudaFuncAttributeMaxDynamicSharedMemorySize,
                         (int)smem);

    transpose_kernel<<<dim3(HW * HW / 32, CC / 32, BB), dim3(32, 32)>>>(f2);
    pool_all_kernel<<<BB * 1344, 256>>>();
    hist_kernel<<<32, 256>>>(cen);
    corr_kernel<<<NBINS * 4, 256, smem>>>(f1, cen);
    out_transpose_kernel<<<dim3(MM / 32, 11, BB), dim3(32, 32)>>>(out);
}

// round 14
// speedup vs baseline: 1.5120x; 1.0184x over previous
#include <cuda_runtime.h>
#include <math.h>

#define BB 2
#define MM 4096
#define CC 256
#define HW 64
#define NBINS 512
#define QCAP 96
#define NPOS_MAX 169
#define PSTRH 132                 // position stride in floats (gmem AND smem)
#define DSTR 172
#define PW0 73
#define TOTPOS 7924               // 73^2 + 41^2 + 25^2 + 17^2

// padded pyramid: [b][half][pos][132]
__device__ __align__(1024) float g_pyr2[BB * 2 * TOTPOS * PSTRH];
__device__ int g_cnt[NBINS];
__device__ int g_qlist[NBINS * QCAP];
__device__ float g_outT[BB * MM * 324];   // [b][m][324] coalesced scratch

__constant__ int c_lvl_base[4] = {0, 5329, 7010, 7635};
__constant__ int c_lvl_pw[4]   = {73, 41, 25, 17};

// ---------------- helpers ---------------------------------------------------
__device__ __forceinline__ void fma2(unsigned long long& d, unsigned long long a,
                                     unsigned long long b) {
    asm("fma.rn.f32x2 %0, %1, %2, %0;" : "+l"(d) : "l"(a), "l"(b));
}
__device__ __forceinline__ float unpack_sum(unsigned long long v) {
    return __uint_as_float((unsigned)v) + __uint_as_float((unsigned)(v >> 32));
}
__device__ __forceinline__ void bulkcp(unsigned dst, const void* src,
                                       unsigned bytes, unsigned mbar) {
    asm volatile("cp.async.bulk.shared::cluster.global.mbarrier::complete_tx::bytes "
                 "[%0], [%1], %2, [%3];" :: "r"(dst), "l"(src), "r"(bytes), "r"(mbar)
                 : "memory");
}
__device__ __forceinline__ void mbar_init(unsigned mbar, unsigned cnt) {
    asm volatile("mbarrier.init.shared.b64 [%0], %1;" :: "r"(mbar), "r"(cnt) : "memory");
}
__device__ __forceinline__ void mbar_expect(unsigned mbar, unsigned bytes) {
    asm volatile("mbarrier.arrive.expect_tx.shared.b64 _, [%0], %1;"
                 :: "r"(mbar), "r"(bytes) : "memory");
}
__device__ __forceinline__ void mbar_wait(unsigned mbar, unsigned parity) {
    unsigned done;
    asm volatile("{\n\t.reg .pred p;\n\t"
                 "mbarrier.try_wait.parity.shared.b64 p, [%1], %2;\n\t"
                 "selp.b32 %0, 1, 0, p;\n\t}" : "=r"(done) : "r"(mbar), "r"(parity)
                 : "memory");
    while (!done)
        asm volatile("{\n\t.reg .pred p;\n\t"
                     "mbarrier.try_wait.parity.shared.b64 p, [%1], %2, 0x989680;\n\t"
                     "selp.b32 %0, 1, 0, p;\n\t}" : "=r"(done)
                     : "r"(mbar), "r"(parity) : "memory");
}

// ---------------- kernel 1: transpose + zero counters -----------------------
__global__ void transpose_kernel(const float* __restrict__ f2) {
    __shared__ float tile[32][33];
    int b = blockIdx.z, p0 = blockIdx.x * 32, c0 = blockIdx.y * 32;
    int tx = threadIdx.x, ty = threadIdx.y;
    if (blockIdx.x == 0 && blockIdx.y == 0 && blockIdx.z == 0) {
        int t = ty * 32 + tx;
        if (t < NBINS) g_cnt[t] = 0;
    }
    tile[ty][tx] = f2[((size_t)b * CC + (c0 + ty)) * (HW * HW) + p0 + tx];
    __syncthreads();
    int p = p0 + ty, y = p >> 6, x = p & 63;
    int c = c0 + tx, h = c >> 7, cc = c & 127;
    int pos = (y + 4) * PW0 + (x + 4);
    g_pyr2[((size_t)(b * 2 + h) * TOTPOS + pos) * PSTRH + cc] = tile[tx][ty];
}

// ---------------- kernel 2: all pooled levels from L0 ------------------------
__global__ void pool_all_kernel() {
    int r = blockIdx.x;
    int b = r / 1344, t = r - b * 1344;
    int l, W, i;
    if (t < 1024)      { l = 1; W = 32; i = t; }
    else if (t < 1280) { l = 2; W = 16; i = t - 1024; }
    else               { l = 3; W = 8;  i = t - 1280; }
    int y = i / W, x = i - (i / W) * W;
    int S = 1 << l;
    int c = threadIdx.x;
    int h = c >> 7, cc = c & 127;
    const float* in = g_pyr2 + (size_t)(b * 2 + h) * TOTPOS * PSTRH + cc;
    float s = 0.f;
    for (int dy = 0; dy < S; dy++)
        for (int dx = 0; dx < S; dx++)
            s += in[(size_t)((y * S + dy + 4) * PW0 + (x * S + dx + 4)) * PSTRH];
    g_pyr2[((size_t)(b * 2 + h) * TOTPOS + c_lvl_base[l]
            + (y + 4) * c_lvl_pw[l] + (x + 4)) * PSTRH + cc] = s / (float)(S * S);
}

// ---------------- kernel 3: histogram + halo zeroing ------------------------
__global__ void hist_kernel(const float* __restrict__ cen) {
    int t = blockIdx.x * blockDim.x + threadIdx.x;

    for (int p = t; p < BB * 2 * TOTPOS; p += 32 * 256) {
        int pp = p % TOTPOS;
        int l = pp < 5329 ? 0 : (pp < 7010 ? 1 : (pp < 7635 ? 2 : 3));
        int pwl = c_lvl_pw[l];
        int r = pp - c_lvl_base[l];
        int y = r / pwl, x = r - (r / pwl) * pwl;
        int W = pwl - 9;
        if (x < 4 || x >= W + 4 || y < 4 || y >= W + 4) {
            float4* dst = (float4*)(g_pyr2 + (size_t)p * PSTRH);
            #pragma unroll 4
            for (int i = 0; i < PSTRH / 4; i++) dst[i] = make_float4(0.f, 0.f, 0.f, 0.f);
        }
    }

    if (t < BB * MM) {
        float cx = cen[2 * t], cy = cen[2 * t + 1];
        int bx = ((int)cx) >> 2;  bx = bx < 0 ? 0 : (bx > 15 ? 15 : bx);
        int by = ((int)cy) >> 2;  by = by < 0 ? 0 : (by > 15 ? 15 : by);
        int b = t / MM, m = t - b * MM;
        int bin = (b << 8) | (by << 4) | bx;
        int pos = atomicAdd(&g_cnt[bin], 1);
        if (pos < QCAP) g_qlist[bin * QCAP + pos] = m;
    }
}

// ---------------- GEMM inner loop: 4q x 4 strips (32 pos) per warp ----------
template <int NQI>
__device__ __forceinline__ void gemm_half(const float* __restrict__ As,
                                          const float* __restrict__ Ps,
                                          int qsel, const int* poff,
                                          unsigned long long acc[4][4]) {
    #pragma unroll 2
    for (int c = 0; c < 128; c += 4) {
        ulonglong2 a[NQI], p[4];
        #pragma unroll
        for (int qi = 0; qi < NQI; qi++)
            a[qi] = *(const ulonglong2*)&As[(qsel + 4 * qi) * PSTRH + c];
        #pragma unroll
        for (int pi = 0; pi < 4; pi++)
            p[pi] = *(const ulonglong2*)&Ps[poff[pi] + c];
        #pragma unroll
        for (int qi = 0; qi < NQI; qi++)
            #pragma unroll
            for (int pi = 0; pi < 4; pi++) {
                fma2(acc[qi][pi], a[qi].x, p[pi].x);
                fma2(acc[qi][pi], a[qi].y, p[pi].y);
            }
    }
}

__global__ __launch_bounds__(256, 2) void corr_kernel(const float* __restrict__ f1,
                                                      const float* __restrict__ cen) {
    extern __shared__ float sm[];
    float* Ps = sm;                           // 169*132
    float* As = sm + NPOS_MAX * PSTRH;        // 16*132
    float* Ds = As + 16 * PSTRH;              // 16*172
    __shared__ __align__(8) unsigned long long mbar_s;

    int blk = blockIdx.x;
    int lvl = blk >> 9, bin = blk & 511;      // LPT: all L0 items first
    int b = bin >> 8, by = (bin >> 4) & 15, bx = bin & 15;
    int nq = g_cnt[bin]; if (nq > QCAP) nq = QCAP;
    if (nq == 0) return;

    int ixmin = (4 * bx) >> lvl, ixmax = (4 * bx + 3) >> lvl;
    int iymin = (4 * by) >> lvl, iymax = (4 * by + 3) >> lvl;
    int px0 = ixmin - 4, py0 = iymin - 4;
    int pw = ixmax - ixmin + 10, ph = iymax - iymin + 10;
    int Npos = pw * ph;
    int pwp = c_lvl_pw[lvl];

    int tid = threadIdx.x, lane = tid & 31, w = tid >> 5;
    int qsel = lane >> 3, psel = lane & 7;
    int wbase = w * 32;
    bool act = wbase < Npos;
    float scale = 1.0f / (float)(1 << lvl);

    unsigned Ps_b = (unsigned)__cvta_generic_to_shared(Ps);
    unsigned As_b = (unsigned)__cvta_generic_to_shared(As);
    unsigned mbar = (unsigned)__cvta_generic_to_shared(&mbar_s);

    if (tid == 0) mbar_init(mbar, 1);
    __syncthreads();
    unsigned par = 0;

    int poff[4];
    #pragma unroll
    for (int pi = 0; pi < 4; pi++) {
        int p = wbase + psel + 8 * pi;
        poff[pi] = ((p < Npos) ? p : (Npos - 1)) * PSTRH;
    }

    unsigned rowB = (unsigned)(pw * PSTRH * 4);   // bytes per contiguous patch row

    for (int q0 = 0; q0 < nq; q0 += 16) {
        int qcnt = nq - q0; if (qcnt > 16) qcnt = 16;
        int nqi = (qcnt + 3) >> 2;            // 1..4, uniform across warps

        unsigned long long acc[4][4];
        #pragma unroll
        for (int qi = 0; qi < 4; qi++)
            #pragma unroll
            for (int pi = 0; pi < 4; pi++) acc[qi][pi] = 0ull;

        for (int h = 0; h < 2; h++) {
            __syncthreads();   // previous phase's smem fully consumed
            if (tid == 0)
                mbar_expect(mbar, (unsigned)Npos * (PSTRH * 4u)
                                  + (unsigned)qcnt * 512u);

            const float* pbase = g_pyr2
                + ((size_t)(b * 2 + h) * TOTPOS + c_lvl_base[lvl]
                   + (size_t)(py0 + 4) * pwp + (px0 + 4)) * PSTRH;
            // row-granular patch staging: ph ops of pw*528 B (contiguous both sides)
            if (tid < ph) {
                bulkcp(Ps_b + (unsigned)(tid * pw * PSTRH) * 4u,
                       pbase + (size_t)tid * pwp * PSTRH, rowB, mbar);
            } else if (tid < ph + qcnt) {
                int qq = tid - ph;
                int m = g_qlist[bin * QCAP + q0 + qq];
                bulkcp(As_b + (unsigned)(qq * PSTRH) * 4u,
                       f1 + ((size_t)b * MM + m) * CC + h * 128, 512u, mbar);
            }
            mbar_wait(mbar, par);
            par ^= 1;

            if (act) {
                switch (nqi) {
                    case 4: gemm_half<4>(As, Ps, qsel, poff, acc); break;
                    case 3: gemm_half<3>(As, Ps, qsel, poff, acc); break;
                    case 2: gemm_half<2>(As, Ps, qsel, poff, acc); break;
                    default: gemm_half<1>(As, Ps, qsel, poff, acc); break;
                }
            }
        }

        // ---- write D -------------------------------------------------------
        if (act) {
            #pragma unroll
            for (int pi = 0; pi < 4; pi++) {
                int p = wbase + psel + 8 * pi;
                if (p < Npos) {
                    #pragma unroll
                    for (int qi = 0; qi < 4; qi++)
                        Ds[(qsel + 4 * qi) * DSTR + p] = unpack_sum(acc[qi][pi]);
                }
            }
        }
        __syncthreads();

        // ---- bilinear epilogue: warp per query, coalesced scratch writes ---
        for (int qq = w; qq < qcnt; qq += 8) {
            int m = g_qlist[bin * QCAP + q0 + qq];
            float cx = cen[((size_t)b * MM + m) * 2 + 0];
            float cy = cen[((size_t)b * MM + m) * 2 + 1];
            float sx = cx * scale, sy = cy * scale;
            float fix = floorf(sx), fiy = floorf(sy);
            float fx = sx - fix, fy = sy - fiy;
            int ox = (int)fix - 4 - px0;
            int oy = (int)fiy - 4 - py0;
            float wx1 = fx, wx0 = 1.f - fx, wy1 = fy, wy0 = 1.f - fy;
            const float* Dq = Ds + qq * DSTR;
            float* dst = g_outT + ((size_t)b * MM + m) * 324 + lvl * 81;
            for (int e = lane; e < 81; e += 32) {
                int i = e / 9, j = e - (e / 9) * 9;
                int base = (oy + j) * pw + (ox + i);
                float d00 = Dq[base],      d01 = Dq[base + 1];
                float d10 = Dq[base + pw], d11 = Dq[base + pw + 1];
                dst[e] = wy0 * (wx0 * d00 + wx1 * d01)
                       + wy1 * (wx0 * d10 + wx1 * d11);
            }
        }
    }
}

// ---------------- kernel 5: transpose scratch -> out (B, 324, M) ------------
// Coalesced on BOTH sides: load lanes sweep the contiguous 324-dim of g_outT,
// store lanes sweep the contiguous M-dim of out.
__global__ void out_transpose_kernel(float* __restrict__ out) {
    __shared__ float tile[32][33];
    int b = blockIdx.z;
    int m0 = blockIdx.x * 32, e0 = blockIdx.y * 32;
    int tx = threadIdx.x, ty = threadIdx.y;
    int el = e0 + tx;
    if (el < 324)
        tile[ty][tx] = g_outT[((size_t)b * MM + m0 + ty) * 324 + el];
    __syncthreads();
    int es = e0 + ty;
    if (es < 324)
        out[((size_t)b * 324 + es) * MM + m0 + tx] = tile[tx][ty];
}

// ---------------- launch ----------------------------------------------------
extern "C" void kernel_launch(void* const* d_in, const int* in_sizes, int n_in,
                              void* d_out, int out_size) {
    const float* f1  = (const float*)d_in[0];
    const float* f2  = (const float*)d_in[1];
    const float* cen = (const float*)d_in[2];
    float* out = (float*)d_out;

    size_t smem = (size_t)(NPOS_MAX * PSTRH + 16 * PSTRH + 16 * DSTR) * sizeof(float);
    cudaFuncSetAttribute(corr_kernel, cudaFuncAttributeMaxDynamicSharedMemorySize,
                         (int)smem);

    transpose_kernel<<<dim3(HW * HW / 32, CC / 32, BB), dim3(32, 32)>>>(f2);
    pool_all_kernel<<<BB * 1344, 256>>>();
    hist_kernel<<<32, 256>>>(cen);
    corr_kernel<<<NBINS * 4, 256, smem>>>(f1, cen);
    out_transpose_kernel<<<dim3(MM / 32, 11, BB), dim3(32, 32)>>>(out);
}

// round 15
// speedup vs baseline: 1.5287x; 1.0110x over previous
#include <cuda_runtime.h>
#include <math.h>

#define BB 2
#define MM 4096
#define CC 256
#define HW 64
#define NBINS 512
#define QCAP 96
#define NPOS_MAX 169
#define PSTRH 132                 // position stride in floats (gmem AND smem)
#define DSTR 172
#define PW0 73
#define TOTPOS 7924               // 73^2 + 41^2 + 25^2 + 17^2
#define POOLBLKS (BB * 1344)

// padded pyramid: [b][half][pos][132]
__device__ __align__(1024) float g_pyr2[BB * 2 * TOTPOS * PSTRH];
__device__ int g_cnt[NBINS];
__device__ int g_qlist[NBINS * QCAP];
__device__ float g_outT[BB * MM * 324];   // [b][m][324] coalesced scratch

__constant__ int c_lvl_base[4] = {0, 5329, 7010, 7635};
__constant__ int c_lvl_pw[4]   = {73, 41, 25, 17};

// ---------------- helpers ---------------------------------------------------
__device__ __forceinline__ void fma2(unsigned long long& d, unsigned long long a,
                                     unsigned long long b) {
    asm("fma.rn.f32x2 %0, %1, %2, %0;" : "+l"(d) : "l"(a), "l"(b));
}
__device__ __forceinline__ float unpack_sum(unsigned long long v) {
    return __uint_as_float((unsigned)v) + __uint_as_float((unsigned)(v >> 32));
}
__device__ __forceinline__ void bulkcp(unsigned dst, const void* src,
                                       unsigned bytes, unsigned mbar) {
    asm volatile("cp.async.bulk.shared::cluster.global.mbarrier::complete_tx::bytes "
                 "[%0], [%1], %2, [%3];" :: "r"(dst), "l"(src), "r"(bytes), "r"(mbar)
                 : "memory");
}
__device__ __forceinline__ void mbar_init(unsigned mbar, unsigned cnt) {
    asm volatile("mbarrier.init.shared.b64 [%0], %1;" :: "r"(mbar), "r"(cnt) : "memory");
}
__device__ __forceinline__ void mbar_expect(unsigned mbar, unsigned bytes) {
    asm volatile("mbarrier.arrive.expect_tx.shared.b64 _, [%0], %1;"
                 :: "r"(mbar), "r"(bytes) : "memory");
}
__device__ __forceinline__ void mbar_wait(unsigned mbar, unsigned parity) {
    unsigned done;
    asm volatile("{\n\t.reg .pred p;\n\t"
                 "mbarrier.try_wait.parity.shared.b64 p, [%1], %2;\n\t"
                 "selp.b32 %0, 1, 0, p;\n\t}" : "=r"(done) : "r"(mbar), "r"(parity)
                 : "memory");
    while (!done)
        asm volatile("{\n\t.reg .pred p;\n\t"
                     "mbarrier.try_wait.parity.shared.b64 p, [%1], %2, 0x989680;\n\t"
                     "selp.b32 %0, 1, 0, p;\n\t}" : "=r"(done)
                     : "r"(mbar), "r"(parity) : "memory");
}

// ---------------- kernel 1: transpose + zero counters -----------------------
__global__ void transpose_kernel(const float* __restrict__ f2) {
    __shared__ float tile[32][33];
    int b = blockIdx.z, p0 = blockIdx.x * 32, c0 = blockIdx.y * 32;
    int tx = threadIdx.x, ty = threadIdx.y;
    if (blockIdx.x == 0 && blockIdx.y == 0 && blockIdx.z == 0) {
        int t = ty * 32 + tx;
        if (t < NBINS) g_cnt[t] = 0;
    }
    tile[ty][tx] = f2[((size_t)b * CC + (c0 + ty)) * (HW * HW) + p0 + tx];
    __syncthreads();
    int p = p0 + ty, y = p >> 6, x = p & 63;
    int c = c0 + tx, h = c >> 7, cc = c & 127;
    int pos = (y + 4) * PW0 + (x + 4);
    g_pyr2[((size_t)(b * 2 + h) * TOTPOS + pos) * PSTRH + cc] = tile[tx][ty];
}

// ---------------- kernel 2: pooled levels + histogram + halo zero (fused) ---
__global__ void pool_hist_kernel(const float* __restrict__ cen) {
    int r = blockIdx.x;
    if (r < POOLBLKS) {
        // ---- pooling: all levels straight from L0 ----
        int b = r / 1344, t = r - b * 1344;
        int l, W, i;
        if (t < 1024)      { l = 1; W = 32; i = t; }
        else if (t < 1280) { l = 2; W = 16; i = t - 1024; }
        else               { l = 3; W = 8;  i = t - 1280; }
        int y = i / W, x = i - (i / W) * W;
        int S = 1 << l;
        int c = threadIdx.x;
        int h = c >> 7, cc = c & 127;
        const float* in = g_pyr2 + (size_t)(b * 2 + h) * TOTPOS * PSTRH + cc;
        float s = 0.f;
        for (int dy = 0; dy < S; dy++)
            for (int dx = 0; dx < S; dx++)
                s += in[(size_t)((y * S + dy + 4) * PW0 + (x * S + dx + 4)) * PSTRH];
        g_pyr2[((size_t)(b * 2 + h) * TOTPOS + c_lvl_base[l]
                + (y + 4) * c_lvl_pw[l] + (x + 4)) * PSTRH + cc] = s / (float)(S * S);
    } else {
        // ---- histogram + halo zeroing (32 blocks) ----
        int t = (r - POOLBLKS) * blockDim.x + threadIdx.x;

        for (int p = t; p < BB * 2 * TOTPOS; p += 32 * 256) {
            int pp = p % TOTPOS;
            int l = pp < 5329 ? 0 : (pp < 7010 ? 1 : (pp < 7635 ? 2 : 3));
            int pwl = c_lvl_pw[l];
            int rr = pp - c_lvl_base[l];
            int y = rr / pwl, x = rr - (rr / pwl) * pwl;
            int W = pwl - 9;
            if (x < 4 || x >= W + 4 || y < 4 || y >= W + 4) {
                float4* dst = (float4*)(g_pyr2 + (size_t)p * PSTRH);
                #pragma unroll 4
                for (int i = 0; i < PSTRH / 4; i++)
                    dst[i] = make_float4(0.f, 0.f, 0.f, 0.f);
            }
        }

        if (t < BB * MM) {
            float cx = cen[2 * t], cy = cen[2 * t + 1];
            int bx = ((int)cx) >> 2;  bx = bx < 0 ? 0 : (bx > 15 ? 15 : bx);
            int by = ((int)cy) >> 2;  by = by < 0 ? 0 : (by > 15 ? 15 : by);
            int b = t / MM, m = t - b * MM;
            int bin = (b << 8) | (by << 4) | bx;
            int pos = atomicAdd(&g_cnt[bin], 1);
            if (pos < QCAP) g_qlist[bin * QCAP + pos] = m;
        }
    }
}

// ---------------- GEMM inner loop: 4q x 4 strips (32 pos) per warp ----------
template <int NQI>
__device__ __forceinline__ void gemm_half(const float* __restrict__ As,
                                          const float* __restrict__ Ps,
                                          int qsel, const int* poff,
                                          unsigned long long acc[4][4]) {
    #pragma unroll 2
    for (int c = 0; c < 128; c += 4) {
        ulonglong2 a[NQI], p[4];
        #pragma unroll
        for (int qi = 0; qi < NQI; qi++)
            a[qi] = *(const ulonglong2*)&As[(qsel + 4 * qi) * PSTRH + c];
        #pragma unroll
        for (int pi = 0; pi < 4; pi++)
            p[pi] = *(const ulonglong2*)&Ps[poff[pi] + c];
        #pragma unroll
        for (int qi = 0; qi < NQI; qi++)
            #pragma unroll
            for (int pi = 0; pi < 4; pi++) {
                fma2(acc[qi][pi], a[qi].x, p[pi].x);
                fma2(acc[qi][pi], a[qi].y, p[pi].y);
            }
    }
}

__global__ __launch_bounds__(256, 2) void corr_kernel(const float* __restrict__ f1,
                                                      const float* __restrict__ cen) {
    extern __shared__ float sm[];
    float* Ps = sm;                           // 169*132
    float* As = sm + NPOS_MAX * PSTRH;        // 16*132
    float* Ds = As + 16 * PSTRH;              // 16*172
    __shared__ __align__(8) unsigned long long mbar_s;

    int blk = blockIdx.x;
    int chunk = blk >> 11;                    // 0 or 1
    int rest = blk & 2047;
    int lvl = rest >> 9, bin = rest & 511;    // LPT: all L0 items first
    int b = bin >> 8, by = (bin >> 4) & 15, bx = bin & 15;
    int nq = g_cnt[bin]; if (nq > QCAP) nq = QCAP;
    if (nq <= 16 * chunk) return;             // chunk-1 blocks exit if nq <= 16

    int ixmin = (4 * bx) >> lvl, ixmax = (4 * bx + 3) >> lvl;
    int iymin = (4 * by) >> lvl, iymax = (4 * by + 3) >> lvl;
    int px0 = ixmin - 4, py0 = iymin - 4;
    int pw = ixmax - ixmin + 10, ph = iymax - iymin + 10;
    int Npos = pw * ph;
    int pwp = c_lvl_pw[lvl];

    int tid = threadIdx.x, lane = tid & 31, w = tid >> 5;
    int qsel = lane >> 3, psel = lane & 7;
    int wbase = w * 32;
    bool act = wbase < Npos;
    float scale = 1.0f / (float)(1 << lvl);

    unsigned Ps_b = (unsigned)__cvta_generic_to_shared(Ps);
    unsigned As_b = (unsigned)__cvta_generic_to_shared(As);
    unsigned mbar = (unsigned)__cvta_generic_to_shared(&mbar_s);

    if (tid == 0) mbar_init(mbar, 1);
    __syncthreads();
    unsigned par = 0;

    int poff[4];
    #pragma unroll
    for (int pi = 0; pi < 4; pi++) {
        int p = wbase + psel + 8 * pi;
        poff[pi] = ((p < Npos) ? p : (Npos - 1)) * PSTRH;
    }

    unsigned rowB = (unsigned)(pw * PSTRH * 4);   // bytes per contiguous patch row

    for (int q0 = 16 * chunk; q0 < nq; q0 += 32) {
        int qcnt = nq - q0; if (qcnt > 16) qcnt = 16;
        int nqi = (qcnt + 3) >> 2;            // 1..4, uniform across warps

        unsigned long long acc[4][4];
        #pragma unroll
        for (int qi = 0; qi < 4; qi++)
            #pragma unroll
            for (int pi = 0; pi < 4; pi++) acc[qi][pi] = 0ull;

        for (int h = 0; h < 2; h++) {
            __syncthreads();   // previous phase's smem fully consumed
            if (tid == 0)
                mbar_expect(mbar, (unsigned)Npos * (PSTRH * 4u)
                                  + (unsigned)qcnt * 512u);

            const float* pbase = g_pyr2
                + ((size_t)(b * 2 + h) * TOTPOS + c_lvl_base[lvl]
                   + (size_t)(py0 + 4) * pwp + (px0 + 4)) * PSTRH;
            // row-granular patch staging: ph ops of pw*528 B (contiguous both sides)
            if (tid < ph) {
                bulkcp(Ps_b + (unsigned)(tid * pw * PSTRH) * 4u,
                       pbase + (size_t)tid * pwp * PSTRH, rowB, mbar);
            } else if (tid < ph + qcnt) {
                int qq = tid - ph;
                int m = g_qlist[bin * QCAP + q0 + qq];
                bulkcp(As_b + (unsigned)(qq * PSTRH) * 4u,
                       f1 + ((size_t)b * MM + m) * CC + h * 128, 512u, mbar);
            }
            mbar_wait(mbar, par);
            par ^= 1;

            if (act) {
                switch (nqi) {
                    case 4: gemm_half<4>(As, Ps, qsel, poff, acc); break;
                    case 3: gemm_half<3>(As, Ps, qsel, poff, acc); break;
                    case 2: gemm_half<2>(As, Ps, qsel, poff, acc); break;
                    default: gemm_half<1>(As, Ps, qsel, poff, acc); break;
                }
            }
        }

        // ---- write D -------------------------------------------------------
        if (act) {
            #pragma unroll
            for (int pi = 0; pi < 4; pi++) {
                int p = wbase + psel + 8 * pi;
                if (p < Npos) {
                    #pragma unroll
                    for (int qi = 0; qi < 4; qi++)
                        Ds[(qsel + 4 * qi) * DSTR + p] = unpack_sum(acc[qi][pi]);
                }
            }
        }
        __syncthreads();

        // ---- bilinear epilogue: warp per query, coalesced scratch writes ---
        for (int qq = w; qq < qcnt; qq += 8) {
            int m = g_qlist[bin * QCAP + q0 + qq];
            float cx = cen[((size_t)b * MM + m) * 2 + 0];
            float cy = cen[((size_t)b * MM + m) * 2 + 1];
            float sx = cx * scale, sy = cy * scale;
            float fix = floorf(sx), fiy = floorf(sy);
            float fx = sx - fix, fy = sy - fiy;
            int ox = (int)fix - 4 - px0;
            int oy = (int)fiy - 4 - py0;
            float wx1 = fx, wx0 = 1.f - fx, wy1 = fy, wy0 = 1.f - fy;
            const float* Dq = Ds + qq * DSTR;
            float* dst = g_outT + ((size_t)b * MM + m) * 324 + lvl * 81;
            for (int e = lane; e < 81; e += 32) {
                int i = e / 9, j = e - (e / 9) * 9;
                int base = (oy + j) * pw + (ox + i);
                float d00 = Dq[base],      d01 = Dq[base + 1];
                float d10 = Dq[base + pw], d11 = Dq[base + pw + 1];
                dst[e] = wy0 * (wx0 * d00 + wx1 * d01)
                       + wy1 * (wx0 * d10 + wx1 * d11);
            }
        }
    }
}

// ---------------- kernel 5: transpose scratch -> out (B, 324, M) ------------
__global__ void out_transpose_kernel(float* __restrict__ out) {
    __shared__ float tile[32][33];
    int b = blockIdx.z;
    int m0 = blockIdx.x * 32, e0 = blockIdx.y * 32;
    int tx = threadIdx.x, ty = threadIdx.y;
    int el = e0 + tx;
    if (el < 324)
        tile[ty][tx] = g_outT[((size_t)b * MM + m0 + ty) * 324 + el];
    __syncthreads();
    int es = e0 + ty;
    if (es < 324)
        out[((size_t)b * 324 + es) * MM + m0 + tx] = tile[tx][ty];
}

// ---------------- launch ----------------------------------------------------
extern "C" void kernel_launch(void* const* d_in, const int* in_sizes, int n_in,
                              void* d_out, int out_size) {
    const float* f1  = (const float*)d_in[0];
    const float* f2  = (const float*)d_in[1];
    const float* cen = (const float*)d_in[2];
    float* out = (float*)d_out;

    size_t smem = (size_t)(NPOS_MAX * PSTRH + 16 * PSTRH + 16 * DSTR) * sizeof(float);
    cudaFuncSetAttribute(corr_kernel, cudaFuncAttributeMaxDynamicSharedMemorySize,
                         (int)smem);

    transpose_kernel<<<dim3(HW * HW / 32, CC / 32, BB), dim3(32, 32)>>>(f2);
    pool_hist_kernel<<<POOLBLKS + 32, 256>>>(cen);
    corr_kernel<<<NBINS * 4 * 2, 256, smem>>>(f1, cen);
    out_transpose_kernel<<<dim3(MM / 32, 11, BB), dim3(32, 32)>>>(out);
}